// round 11
// baseline (speedup 1.0000x reference)
#include <cuda_runtime.h>
#include <cstdint>

// VanillaRNN B=128,S=2048,E=256,H=512,V=128 fp32 — persistent kernel v7.
// Round-10: 16 row-groups x 8 CTAs (CTA = 8 B-rows x 64 H-cols), each
// row-group is one 8-CTA cluster. Sync via cluster mbarriers (remote
// arrive + local try_wait) instead of a global atomic counter. One
// butterfly pre-reduce level halves the SMEM partials (16 slices).
// Warp = one 8-col group; lanes = 32 k-slices; LDS conflict-free.

#define Bb   128
#define Ss   2048
#define Vv   128
#define Ee   256
#define Hh   512
#define NBLK 128
#define NTHR 256

#define RR_STRIDE 516        // Δbank 4 per slice row -> conflict-free

// SMEM offsets (floats)
#define OFF_SH   0                       // h tile: 8 x 512 (plain)
#define OFF_WH   4096                    // Wh slice: 512 k x 64 c (unit-XOR)
#define OFF_WF   36864                   // Wfc slice: 16 cols x 512 k
#define OFF_RR   45056                   // partials: 16 x 516
#define OFF_MBAR 53312                   // mbarrier (8B)
#define SMEM_FLOATS 53316
#define SMEM_BYTES  (SMEM_FLOATS * 4)

__device__ float g_h[2][Bb * Hh];        // double-buffered hidden state
__device__ float g_xw[Vv * Hh];          // token -> (emb@Wx + bx + bh)

static __device__ __forceinline__ float2 ffma2(float2 a, float2 b, float2 c) {
    union { float2 f; unsigned long long u; } A, B2, C;
    A.f = a; B2.f = b; C.f = c;
    asm("fma.rn.f32x2 %0, %1, %2, %0;" : "+l"(C.u) : "l"(A.u), "l"(B2.u));
    return C.f;
}

// one recursive-halving butterfly round over float2 array v[m]
#define BFLY2(v, m, s) {                                                  \
    const int  half_ = (m) >> 1;                                          \
    const bool up_ = (lane & (s)) != 0;                                   \
    _Pragma("unroll")                                                     \
    for (int i_ = 0; i_ < half_; ++i_) {                                  \
        float2 d_ = up_ ? v[i_] : v[i_ + half_];                          \
        float2 o_;                                                        \
        o_.x = __shfl_xor_sync(0xffffffffu, d_.x, (s));                   \
        o_.y = __shfl_xor_sync(0xffffffffu, d_.y, (s));                   \
        float2 k_ = up_ ? v[i_ + half_] : v[i_];                          \
        v[i_].x = k_.x + o_.x;                                            \
        v[i_].y = k_.y + o_.y;                                            \
    } }

__global__ void rnn_init_kernel() {
    int idx = blockIdx.x * blockDim.x + threadIdx.x;
    for (int i = idx; i < Bb * Hh; i += gridDim.x * blockDim.x)
        g_h[1][i] = 0.0f;                // h_{-1} = 0 (read at t=0)
}

// g_xw[v][:] = emb[v] @ Wx + bx + bh   (tiny one-off GEMM)
__global__ void __launch_bounds__(512) xw_kernel(
    const float* __restrict__ emb, const float* __restrict__ Wx,
    const float* __restrict__ bx,  const float* __restrict__ bh)
{
    __shared__ float se[Ee];
    const int v = blockIdx.x, j = threadIdx.x;
    if (j < Ee) se[j] = emb[v * Ee + j];
    __syncthreads();
    float acc = 0.f;
#pragma unroll 8
    for (int e = 0; e < Ee; ++e) acc = fmaf(se[e], Wx[e * Hh + j], acc);
    g_xw[v * Hh + j] = acc + bx[j] + bh[j];
}

__global__ void __launch_bounds__(NTHR, 1) __cluster_dims__(8, 1, 1)
rnn_persistent(const int*   __restrict__ x,
               const float* __restrict__ Wh,
               const float* __restrict__ Wfc,
               const float* __restrict__ bfc,
               float* __restrict__ out)
{
    extern __shared__ float sm[];
    const int tid  = threadIdx.x;
    const int bidx = blockIdx.x;
    const int rgc  = bidx >> 3;          // row-group 0..15 (8 B-rows)
    const int R0   = rgc << 3;
    const int cg   = bidx & 7;           // = cluster rank
    const int C0   = cg << 6;            // 64 H-cols
    const int VC0  = cg << 4;            // 16 V-cols
    const int lane = tid & 31;
    const int ks   = lane;               // k-slice: k = m*128 + ks*4 + ki
    const int w    = tid >> 5;           // warp = col group (8 cols)
    // Wh swizzled unit positions (loop-invariant per lane)
    const int x0u = (w * 2)     ^ (ks & 7);
    const int x1u = (w * 2 + 1) ^ (ks & 7);
    // finalize mapping: thread -> h float2 (row i2, col j2)
    const int i2 = tid >> 5;             // 0..7
    const int j2 = (lane) * 2;           // 0..62
    // V out-path owner row
    const int fr = lane >> 2;            // 0..7

    uint32_t smem_u32;
    asm("{ .reg .u64 t0; cvta.to.shared.u64 t0, %1; cvt.u32.u64 %0, t0; }"
        : "=r"(smem_u32) : "l"(sm));
    const uint32_t mbar = smem_u32 + OFF_MBAR * 4;

    // ---- prologue: weights + mbarrier init + cluster sync --------------
    if (tid == 0)
        asm volatile("mbarrier.init.shared.b64 [%0], %1;"
                     :: "r"(mbar), "r"(64) : "memory");
    for (int idx = tid; idx < Hh * 64; idx += NTHR) {
        const int k = idx >> 6, c = idx & 63;
        const int u2 = (c >> 2) ^ ((k >> 2) & 7);
        sm[OFF_WH + (k << 6) + u2 * 4 + (c & 3)] = Wh[k * Hh + C0 + c];
    }
    for (int idx = tid; idx < 16 * Hh; idx += NTHR) {
        const int c = idx >> 9, k = idx & 511;
        sm[OFF_WF + (c << 9) + k] = Wfc[k * Vv + VC0 + c];
    }
    const float2 bfcv = *(const float2*)(bfc + VC0 + w * 2);
    __syncthreads();
    asm volatile("barrier.cluster.arrive.aligned;" ::: "memory");
    asm volatile("barrier.cluster.wait.aligned;"   ::: "memory");

    const float4* wh4 = (const float4*)(sm + OFF_WH);

    for (int t = 0; t <= Ss; ++t) {
        // ---- wait: all 64 producer warps of the cluster arrived --------
        if (t > 0) {
            const int parity = (t - 1) & 1;
            uint32_t done;
            do {
                asm volatile(
                    "{ .reg .pred p;\n\t"
                    "mbarrier.try_wait.parity.acquire.cluster.shared::cta.b64 "
                    "p, [%1], %2, 0x989680;\n\t"
                    "selp.b32 %0, 1, 0, p; }"
                    : "=r"(done) : "r"(mbar), "r"(parity) : "memory");
            } while (!done);
        }
        // ---- stage h(t-1) 8x512 via cp.async, two overlapped halves ----
        const float* hsrc = g_h[(t + 1) & 1];
#pragma unroll
        for (int q = 0; q < 2; ++q) {           // half A: units 0..63
            const int idx = tid + (q << 8);
            const int row = idx >> 6, u = idx & 63;
            const uint32_t sa = smem_u32 +
                (uint32_t)((OFF_SH + (row << 9) + u * 4) * 4);
            asm volatile("cp.async.cg.shared.global [%0], [%1], 16;"
                :: "r"(sa), "l"(((const float4*)(hsrc + ((R0 + row) << 9))) + u));
        }
        asm volatile("cp.async.commit_group;");
#pragma unroll
        for (int q = 0; q < 2; ++q) {           // half B: units 64..127
            const int idx = tid + (q << 8);
            const int row = idx >> 6, u = 64 + (idx & 63);
            const uint32_t sa = smem_u32 +
                (uint32_t)((OFF_SH + (row << 9) + u * 4) * 4);
            asm volatile("cp.async.cg.shared.global [%0], [%1], 16;"
                :: "r"(sa), "l"(((const float4*)(hsrc + ((R0 + row) << 9))) + u));
        }
        asm volatile("cp.async.commit_group;");

        int tk = 0;
        if (t < Ss) tk = __ldg(x + (R0 + i2) * Ss + t);

        asm volatile("cp.async.wait_group 1;");
        __syncthreads();

        float2 accV[8];
#pragma unroll
        for (int r = 0; r < 8; ++r) accV[r] = make_float2(0.f, 0.f);
        float2 accR[32];
        float2 xa = make_float2(0.f, 0.f);

        if (t < Ss) {
            xa = __ldg((const float2*)(g_xw + tk * Hh + C0 + j2));
#pragma unroll
            for (int p = 0; p < 32; ++p) accR[p] = make_float2(0.f, 0.f);
        }

#pragma unroll
        for (int half = 0; half < 2; ++half) {
            if (half == 1) {
                asm volatile("cp.async.wait_group 0;");
                __syncthreads();
            }
            if (t < Ss) {
#pragma unroll
                for (int mm = 0; mm < 2; ++mm) {
                    const int m  = half * 2 + mm;
                    const int ub = m * 32 + ks;
                    float4 h4[8];
#pragma unroll
                    for (int r = 0; r < 8; ++r)
                        h4[r] = *(const float4*)(sm + OFF_SH + (r << 9) + ub * 4);
                    const float4 wfa = *(const float4*)(sm + OFF_WF
                                  + ((w * 2 + 0) << 9) + ub * 4);
                    const float4 wfb = *(const float4*)(sm + OFF_WF
                                  + ((w * 2 + 1) << 9) + ub * 4);
#pragma unroll
                    for (int ki = 0; ki < 4; ++ki) {
                        const int kk = m * 128 + ks * 4 + ki;
                        const float4 wa = wh4[(kk << 4) + x0u];
                        const float4 wb = wh4[(kk << 4) + x1u];
                        const float2 wv = make_float2(((const float*)&wfa)[ki],
                                                      ((const float*)&wfb)[ki]);
#pragma unroll
                        for (int r = 0; r < 8; ++r) {
                            const float hv = ((const float*)&h4[r])[ki];
                            const float2 hh = make_float2(hv, hv);
                            accR[r*4+0] = ffma2(hh, make_float2(wa.x, wa.y), accR[r*4+0]);
                            accR[r*4+1] = ffma2(hh, make_float2(wa.z, wa.w), accR[r*4+1]);
                            accR[r*4+2] = ffma2(hh, make_float2(wb.x, wb.y), accR[r*4+2]);
                            accR[r*4+3] = ffma2(hh, make_float2(wb.z, wb.w), accR[r*4+3]);
                            accV[r]     = ffma2(hh, wv, accV[r]);
                        }
                    }
                }
            } else if (half == 1) {
                // t == Ss: output projection of h(Ss-1) only
#pragma unroll
                for (int m = 0; m < 4; ++m) {
                    const int ub = m * 32 + ks;
                    const float4 wfa = *(const float4*)(sm + OFF_WF
                                  + ((w * 2 + 0) << 9) + ub * 4);
                    const float4 wfb = *(const float4*)(sm + OFF_WF
                                  + ((w * 2 + 1) << 9) + ub * 4);
#pragma unroll
                    for (int r = 0; r < 8; ++r) {
                        const float4 h4 = *(const float4*)(sm + OFF_SH
                                  + (r << 9) + ub * 4);
#pragma unroll
                        for (int ki = 0; ki < 4; ++ki) {
                            const float hv = ((const float*)&h4)[ki];
                            const float2 wv = make_float2(((const float*)&wfa)[ki],
                                                          ((const float*)&wfb)[ki]);
                            accV[r] = ffma2(make_float2(hv, hv), wv, accV[r]);
                        }
                    }
                }
            }
        }

        if (t < Ss) {
            // ---- one butterfly level: rows 0-3 / 4-7 split over ks^16 --
            BFLY2(accR, 32, 16);
            const int ksl = ks & 15;
            const int rb  = (ks >> 4) * 4;
#pragma unroll
            for (int r = 0; r < 4; ++r) {
                float* dst = sm + OFF_RR + ksl * RR_STRIDE
                             + ((rb + r) << 6) + w * 8;
                *(float4*)dst       = make_float4(accR[r*4+0].x, accR[r*4+0].y,
                                                  accR[r*4+1].x, accR[r*4+1].y);
                *(float4*)(dst + 4) = make_float4(accR[r*4+2].x, accR[r*4+2].y,
                                                  accR[r*4+3].x, accR[r*4+3].y);
            }
            __syncthreads();
            // ---- reduce 16 slices, tanh, publish, remote arrives -------
            float2 s = xa;
#pragma unroll
            for (int sl = 0; sl < 16; ++sl) {
                const float2 v = *(const float2*)(sm + OFF_RR
                                    + sl * RR_STRIDE + tid * 2);
                s.x += v.x; s.y += v.y;
            }
            s.x = tanhf(s.x);
            s.y = tanhf(s.y);
            *(float2*)(&g_h[t & 1][((R0 + i2) << 9) + C0 + j2]) = s;
            __syncwarp();
            if (lane == 0) {
#pragma unroll
                for (int c = 0; c < 8; ++c)
                    asm volatile(
                        "{ .reg .b32 ra;\n\t"
                        "mapa.shared::cluster.u32 ra, %0, %1;\n\t"
                        "mbarrier.arrive.release.cluster.shared::cluster.b64 _, [ra]; }"
                        :: "r"(mbar), "r"(c) : "memory");
            }
        }

        // ---- out(t-1): in-warp V reduce, off inter-CTA critical path ---
        if (t > 0) {
            BFLY2(accV, 8, 16);
            BFLY2(accV, 4,  8);
            BFLY2(accV, 2,  4);
            accV[0].x += __shfl_xor_sync(0xffffffffu, accV[0].x, 2);
            accV[0].y += __shfl_xor_sync(0xffffffffu, accV[0].y, 2);
            accV[0].x += __shfl_xor_sync(0xffffffffu, accV[0].x, 1);
            accV[0].y += __shfl_xor_sync(0xffffffffu, accV[0].y, 1);
            if ((lane & 3) == 0) {
                float2 o = make_float2(accV[0].x + bfcv.x, accV[0].y + bfcv.y);
                *(float2*)(out + (long)(R0 + fr) * (Ss * Vv)
                           + (long)(t - 1) * Vv + VC0 + w * 2) = o;
            }
        }
    }
}

extern "C" void kernel_launch(void* const* d_in, const int* in_sizes, int n_in,
                              void* d_out, int out_size) {
    const int*   x   = (const int*)  d_in[0];
    const float* emb = (const float*)d_in[1];
    const float* Wx  = (const float*)d_in[2];
    const float* bx  = (const float*)d_in[3];
    const float* Wh  = (const float*)d_in[4];
    const float* bh  = (const float*)d_in[5];
    const float* Wfc = (const float*)d_in[6];
    const float* bfc = (const float*)d_in[7];
    float* out = (float*)d_out;

    cudaFuncSetAttribute(rnn_persistent,
                         cudaFuncAttributeMaxDynamicSharedMemorySize, SMEM_BYTES);

    rnn_init_kernel<<<64, 256>>>();
    xw_kernel<<<Vv, 512>>>(emb, Wx, bx, bh);
    rnn_persistent<<<NBLK, NTHR, SMEM_BYTES>>>(x, Wh, Wfc, bfc, out);
}

// round 12
// speedup vs baseline: 1.8182x; 1.8182x over previous
#include <cuda_runtime.h>
#include <cstdint>

// VanillaRNN B=128,S=2048,E=256,H=512,V=128 fp32 — persistent kernel v8.
// Round-11: v6 skeleton (8 row-groups x 16 CTAs, CTA = 16 B-rows x 32 H-cols,
// global-atomic sync) + CHUNKED DATAFLOW: the row-group barrier is split into
// 4 per-k-chunk counters (chunk m <- producer CTAs cg in [4m,4m+4)). Each
// step runs a 4-deep pipeline: poll+stage chunk m+2 overlaps compute of
// chunk m, so producer skew and cp.async fill hide under compute.

#define Bb   128
#define Ss   2048
#define Vv   128
#define Ee   256
#define Hh   512
#define NBLK 128
#define NTHR 256

#define RR_STRIDE 516        // Δbank 4 per slice row -> conflict-free

// SMEM offsets (floats)
#define OFF_SH   0                       // h tile: 16 x 512 (plain layout)
#define OFF_WH   8192                    // Wh slice: 512 k x 32 c (unit-XOR)
#define OFF_WF   24576                   // Wfc slice: 8 cols x 512 k
#define OFF_RR   28672                   // rec partials: 32 x 516
#define SMEM_FLOATS (OFF_RR + 32 * RR_STRIDE)
#define SMEM_BYTES  (SMEM_FLOATS * 4)

__device__ float g_h[2][Bb * Hh];        // double-buffered hidden state
__device__ float g_xw[Vv * Hh];          // token -> (emb@Wx + bx + bh)
__device__ int   g_barc[32 * 32];        // [rowgroup][chunk] counters, 128B apart

static __device__ __forceinline__ float2 ffma2(float2 a, float2 b, float2 c) {
    union { float2 f; unsigned long long u; } A, B2, C;
    A.f = a; B2.f = b; C.f = c;
    asm("fma.rn.f32x2 %0, %1, %2, %0;" : "+l"(C.u) : "l"(A.u), "l"(B2.u));
    return C.f;
}

// one recursive-halving butterfly round over float2 array v[m] (V-path only)
#define BFLY2(v, m, s) {                                                  \
    const int  half_ = (m) >> 1;                                          \
    const bool up_ = (lane & (s)) != 0;                                   \
    _Pragma("unroll")                                                     \
    for (int i_ = 0; i_ < half_; ++i_) {                                  \
        float2 d_ = up_ ? v[i_] : v[i_ + half_];                          \
        float2 o_;                                                        \
        o_.x = __shfl_xor_sync(0xffffffffu, d_.x, (s));                   \
        o_.y = __shfl_xor_sync(0xffffffffu, d_.y, (s));                   \
        float2 k_ = up_ ? v[i_ + half_] : v[i_];                          \
        v[i_].x = k_.x + o_.x;                                            \
        v[i_].y = k_.y + o_.y;                                            \
    } }

__global__ void rnn_init_kernel() {
    int idx = blockIdx.x * blockDim.x + threadIdx.x;
    for (int i = idx; i < Bb * Hh; i += gridDim.x * blockDim.x)
        g_h[1][i] = 0.0f;                // h_{-1} = 0 (read at t=0)
    if (idx < 32 * 32) g_barc[idx] = 0;
}

// g_xw[v][:] = emb[v] @ Wx + bx + bh   (tiny one-off GEMM)
__global__ void __launch_bounds__(512) xw_kernel(
    const float* __restrict__ emb, const float* __restrict__ Wx,
    const float* __restrict__ bx,  const float* __restrict__ bh)
{
    __shared__ float se[Ee];
    const int v = blockIdx.x, j = threadIdx.x;
    if (j < Ee) se[j] = emb[v * Ee + j];
    __syncthreads();
    float acc = 0.f;
#pragma unroll 8
    for (int e = 0; e < Ee; ++e) acc = fmaf(se[e], Wx[e * Hh + j], acc);
    g_xw[v * Hh + j] = acc + bx[j] + bh[j];
}

__global__ void __launch_bounds__(NTHR, 1)
rnn_persistent(const int*   __restrict__ x,
               const float* __restrict__ Wh,
               const float* __restrict__ Wfc,
               const float* __restrict__ bfc,
               float* __restrict__ out)
{
    extern __shared__ float sm[];
    const int tid  = threadIdx.x;
    const int bidx = blockIdx.x;
    const int rgc  = bidx >> 4;          // row-group 0..7 (16 B-rows)
    const int R0   = rgc << 4;
    const int cg   = bidx & 15;
    const int C0   = cg << 5;            // 32 H-cols
    const int VC0  = cg << 3;            // 8 V-cols
    const int lane = tid & 31;
    const int ks   = lane;               // k-slice: k = m*128 + ks*4 + ki
    const int w    = tid >> 5;           // warp 0..7
    const int rowg = w >> 2;             // 0..1  -> rows rowg*8..+7
    const int colg = w & 3;              // 0..3  -> cols colg*8..+7
    const int hrow0 = rowg << 3;
    // this CTA produces k-chunk (cg>>2); its release counter:
    int* mybar = &g_barc[(rgc * 4 + (cg >> 2)) * 32];
    // Wh swizzled unit positions (loop-invariant per lane)
    const int x0u = (colg * 2)     ^ (ks & 7);
    const int x1u = (colg * 2 + 1) ^ (ks & 7);
    // finalize mapping: thread -> h float2 (row i2, col j2)
    const int i2 = tid >> 4;             // 0..15
    const int j2 = (tid & 15) * 2;       // 0..30
    // V out-path owner row
    const int fr = lane >> 2;            // 0..7

    uint32_t smem_u32;
    asm("{ .reg .u64 t0; cvta.to.shared.u64 t0, %1; cvt.u32.u64 %0, t0; }"
        : "=r"(smem_u32) : "l"(sm));

    // ---- prologue: Wh slice (unit-XOR swizzle), Wfc slice --------------
    for (int idx = tid; idx < Hh * 32; idx += NTHR) {
        const int k = idx >> 5, c = idx & 31;
        const int u2 = (c >> 2) ^ ((k >> 2) & 7);
        sm[OFF_WH + (k << 5) + u2 * 4 + (c & 3)] = Wh[k * Hh + C0 + c];
    }
    for (int idx = tid; idx < 8 * Hh; idx += NTHR) {
        const int c = idx >> 9, k = idx & 511;
        sm[OFF_WF + (c << 9) + k] = Wfc[k * Vv + VC0 + c];
    }
    const float2 bfcv = *(const float2*)(bfc + VC0 + colg * 2);
    __syncthreads();

    const float4* wh4 = (const float4*)(sm + OFF_WH);

    for (int t = 0; t <= Ss; ++t) {
        const float* hsrc = g_h[(t + 1) & 1];
        // early token + xw prefetch (independent of h)
        int tk = 0;
        if (t < Ss) tk = __ldg(x + (R0 + i2) * Ss + t);

        float2 accV[8];
#pragma unroll
        for (int r = 0; r < 8; ++r) accV[r] = make_float2(0.f, 0.f);
        float2 accR[32];
#pragma unroll
        for (int p = 0; p < 32; ++p) accR[p] = make_float2(0.f, 0.f);
        float2 xa = make_float2(0.f, 0.f);

        // ---- poll + stage chunk helper (expanded inline) ---------------
        // poll(m): per-warp lane0 acquire-spin on counter, then syncwarp.
        // stage(m): 256 threads cp.async 16 rows x 128 cols (2 float4 each).
#define POLLSTAGE(mm) {                                                   \
        if (t > 0) {                                                      \
            if (lane == 0) {                                              \
                int* bc = &g_barc[(rgc * 4 + (mm)) * 32];                 \
                const int target = t << 5;                                \
                int v;                                                    \
                do {                                                      \
                    asm volatile("ld.acquire.gpu.global.b32 %0, [%1];"    \
                                 : "=r"(v) : "l"(bc) : "memory");         \
                } while (v - target < 0);                                 \
            }                                                             \
            __syncwarp();                                                 \
        }                                                                 \
        _Pragma("unroll")                                                 \
        for (int q = 0; q < 2; ++q) {                                     \
            const int idx = tid + (q << 8);                               \
            const int row = idx >> 5;                                     \
            const int u   = ((mm) << 5) + (idx & 31);                     \
            const uint32_t sa = smem_u32 +                                \
                (uint32_t)((OFF_SH + (row << 9) + u * 4) * 4);            \
            asm volatile("cp.async.cg.shared.global [%0], [%1], 16;"      \
                :: "r"(sa),                                               \
                   "l"(((const float4*)(hsrc + ((R0 + row) << 9))) + u)); \
        }                                                                 \
        asm volatile("cp.async.commit_group;"); }

        POLLSTAGE(0);
        POLLSTAGE(1);
        if (t < Ss)
            xa = __ldg((const float2*)(g_xw + tk * Hh + C0 + j2));

#pragma unroll
        for (int m = 0; m < 4; ++m) {
            if (m < 3) asm volatile("cp.async.wait_group 1;");
            else       asm volatile("cp.async.wait_group 0;");
            __syncthreads();

            const int ub = (m << 5) + ks;
            if (t < Ss) {
                float4 h4[8];
#pragma unroll
                for (int r = 0; r < 8; ++r)
                    h4[r] = *(const float4*)(sm + OFF_SH
                              + ((hrow0 + r) << 9) + ub * 4);
                const float4 wfa = *(const float4*)(sm + OFF_WF
                              + ((colg * 2 + 0) << 9) + ub * 4);
                const float4 wfb = *(const float4*)(sm + OFF_WF
                              + ((colg * 2 + 1) << 9) + ub * 4);
#pragma unroll
                for (int ki = 0; ki < 4; ++ki) {
                    const int k = (m << 7) + (ks << 2) + ki;
                    const float4 wa = wh4[(k << 3) + x0u];
                    const float4 wb = wh4[(k << 3) + x1u];
                    const float2 wv = make_float2(((const float*)&wfa)[ki],
                                                  ((const float*)&wfb)[ki]);
#pragma unroll
                    for (int r = 0; r < 8; ++r) {
                        const float hv = ((const float*)&h4[r])[ki];
                        const float2 hh = make_float2(hv, hv);
                        accR[r*4+0] = ffma2(hh, make_float2(wa.x, wa.y), accR[r*4+0]);
                        accR[r*4+1] = ffma2(hh, make_float2(wa.z, wa.w), accR[r*4+1]);
                        accR[r*4+2] = ffma2(hh, make_float2(wb.x, wb.y), accR[r*4+2]);
                        accR[r*4+3] = ffma2(hh, make_float2(wb.z, wb.w), accR[r*4+3]);
                        accV[r]     = ffma2(hh, wv, accV[r]);
                    }
                }
            } else {
                // t == Ss: output projection of h(Ss-1) only
                const float4 wfa = *(const float4*)(sm + OFF_WF
                              + ((colg * 2 + 0) << 9) + ub * 4);
                const float4 wfb = *(const float4*)(sm + OFF_WF
                              + ((colg * 2 + 1) << 9) + ub * 4);
#pragma unroll
                for (int r = 0; r < 8; ++r) {
                    const float4 h4 = *(const float4*)(sm + OFF_SH
                              + ((hrow0 + r) << 9) + ub * 4);
#pragma unroll
                    for (int ki = 0; ki < 4; ++ki) {
                        const float hv = ((const float*)&h4)[ki];
                        const float2 wv = make_float2(((const float*)&wfa)[ki],
                                                      ((const float*)&wfb)[ki]);
                        accV[r] = ffma2(make_float2(hv, hv), wv, accV[r]);
                    }
                }
            }

            if (m < 2) POLLSTAGE(m + 2);
        }
#undef POLLSTAGE

        if (t < Ss) {
            // ---- write rec partials, reduce 32 slices, tanh, publish ---
#pragma unroll
            for (int r = 0; r < 8; ++r) {
                float* dst = sm + OFF_RR + ks * RR_STRIDE
                             + ((hrow0 + r) << 5) + colg * 8;
                *(float4*)dst       = make_float4(accR[r*4+0].x, accR[r*4+0].y,
                                                  accR[r*4+1].x, accR[r*4+1].y);
                *(float4*)(dst + 4) = make_float4(accR[r*4+2].x, accR[r*4+2].y,
                                                  accR[r*4+3].x, accR[r*4+3].y);
            }
            __syncthreads();
            float2 s = xa;
#pragma unroll
            for (int sl = 0; sl < 32; ++sl) {
                const float2 v = *(const float2*)(sm + OFF_RR
                                    + sl * RR_STRIDE + tid * 2);
                s.x += v.x; s.y += v.y;
            }
            s.x = tanhf(s.x);
            s.y = tanhf(s.y);
            *(float2*)(&g_h[t & 1][((R0 + i2) << 9) + C0 + j2]) = s;
            __syncwarp();
            if (lane == 0)
                asm volatile("red.release.gpu.global.add.s32 [%0], %1;"
                             :: "l"(mybar), "r"(1) : "memory");
        }

        // ---- out(t-1): in-warp V reduce, off inter-CTA critical path ---
        if (t > 0) {
            BFLY2(accV, 8, 16);
            BFLY2(accV, 4,  8);
            BFLY2(accV, 2,  4);
            accV[0].x += __shfl_xor_sync(0xffffffffu, accV[0].x, 2);
            accV[0].y += __shfl_xor_sync(0xffffffffu, accV[0].y, 2);
            accV[0].x += __shfl_xor_sync(0xffffffffu, accV[0].x, 1);
            accV[0].y += __shfl_xor_sync(0xffffffffu, accV[0].y, 1);
            if ((lane & 3) == 0) {
                float2 o = make_float2(accV[0].x + bfcv.x, accV[0].y + bfcv.y);
                *(float2*)(out + (long)(R0 + hrow0 + fr) * (Ss * Vv)
                           + (long)(t - 1) * Vv + VC0 + colg * 2) = o;
            }
        }
    }
}

extern "C" void kernel_launch(void* const* d_in, const int* in_sizes, int n_in,
                              void* d_out, int out_size) {
    const int*   x   = (const int*)  d_in[0];
    const float* emb = (const float*)d_in[1];
    const float* Wx  = (const float*)d_in[2];
    const float* bx  = (const float*)d_in[3];
    const float* Wh  = (const float*)d_in[4];
    const float* bh  = (const float*)d_in[5];
    const float* Wfc = (const float*)d_in[6];
    const float* bfc = (const float*)d_in[7];
    float* out = (float*)d_out;

    cudaFuncSetAttribute(rnn_persistent,
                         cudaFuncAttributeMaxDynamicSharedMemorySize, SMEM_BYTES);

    rnn_init_kernel<<<64, 256>>>();
    xw_kernel<<<Vv, 512>>>(emb, Wx, bx, bh);
    rnn_persistent<<<NBLK, NTHR, SMEM_BYTES>>>(x, Wh, Wfc, bfc, out);
}

// round 13
// speedup vs baseline: 2.3473x; 1.2910x over previous
#include <cuda_runtime.h>
#include <cstdint>

// VanillaRNN B=128,S=2048,E=256,H=512,V=128 fp32 — persistent kernel v9.
// Base = v6 (best: 8 row-groups x 16 CTAs, CTA = 16 B-rows x 32 H-cols,
// two-phase staged step, global-atomic sync). Round-12 local changes:
//  - one in-warp butterfly pre-reduce level -> 16-slice partials (halves
//    the reduce-phase crossbar traffic); bank-safe 145-unit slice stride.
//  - barrier split into two k-half counters; each half polled just before
//    its staging, so late half-B producers hide under compute of half A.
//  - init merged into xw_kernel (fewer launches; ncu lands on the RNN).

#define Bb   128
#define Ss   2048
#define Vv   128
#define Ee   256
#define Hh   512
#define NBLK 128
#define NTHR 256

#define RR_SLICE 580         // floats per slice: 16 rows x 36 + pad (145 units, odd mod 8)

// SMEM offsets (floats)
#define OFF_SH   0                       // h tile: 16 x 512 (plain layout)
#define OFF_WH   8192                    // Wh slice: 512 k x 32 c (unit-XOR)
#define OFF_WF   24576                   // Wfc slice: 8 cols x 512 k
#define OFF_RR   28672                   // partials: 16 x RR_SLICE
#define SMEM_FLOATS (OFF_RR + 16 * RR_SLICE)
#define SMEM_BYTES  (SMEM_FLOATS * 4)

__device__ float g_h[2][Bb * Hh];        // double-buffered hidden state
__device__ float g_xw[Vv * Hh];          // token -> (emb@Wx + bx + bh)
__device__ int   g_barc[16 * 32];        // [rowgroup][half] counters, 128B apart

static __device__ __forceinline__ float2 ffma2(float2 a, float2 b, float2 c) {
    union { float2 f; unsigned long long u; } A, B2, C;
    A.f = a; B2.f = b; C.f = c;
    asm("fma.rn.f32x2 %0, %1, %2, %0;" : "+l"(C.u) : "l"(A.u), "l"(B2.u));
    return C.f;
}

// one recursive-halving butterfly round over float2 array v[m]
#define BFLY2(v, m, s) {                                                  \
    const int  half_ = (m) >> 1;                                          \
    const bool up_ = (lane & (s)) != 0;                                   \
    _Pragma("unroll")                                                     \
    for (int i_ = 0; i_ < half_; ++i_) {                                  \
        float2 d_ = up_ ? v[i_] : v[i_ + half_];                          \
        float2 o_;                                                        \
        o_.x = __shfl_xor_sync(0xffffffffu, d_.x, (s));                   \
        o_.y = __shfl_xor_sync(0xffffffffu, d_.y, (s));                   \
        float2 k_ = up_ ? v[i_ + half_] : v[i_];                          \
        v[i_].x = k_.x + o_.x;                                            \
        v[i_].y = k_.y + o_.y;                                            \
    } }

// g_xw[v][:] = emb[v] @ Wx + bx + bh ; also zeroes h(-1) and counters
__global__ void __launch_bounds__(512) xw_kernel(
    const float* __restrict__ emb, const float* __restrict__ Wx,
    const float* __restrict__ bx,  const float* __restrict__ bh)
{
    __shared__ float se[Ee];
    const int v = blockIdx.x, j = threadIdx.x;
    g_h[1][v * 512 + j] = 0.0f;          // 128 blk x 512 thr = Bb*Hh exactly
    if (v == 0 && j < 16 * 32) g_barc[j] = 0;
    if (j < Ee) se[j] = emb[v * Ee + j];
    __syncthreads();
    float acc = 0.f;
#pragma unroll 8
    for (int e = 0; e < Ee; ++e) acc = fmaf(se[e], Wx[e * Hh + j], acc);
    g_xw[v * Hh + j] = acc + bx[j] + bh[j];
}

__global__ void __launch_bounds__(NTHR, 1)
rnn_persistent(const int*   __restrict__ x,
               const float* __restrict__ Wh,
               const float* __restrict__ Wfc,
               const float* __restrict__ bfc,
               float* __restrict__ out)
{
    extern __shared__ float sm[];
    const int tid  = threadIdx.x;
    const int bidx = blockIdx.x;
    const int rgc  = bidx >> 4;          // row-group 0..7 (16 B-rows)
    const int R0   = rgc << 4;
    const int cg   = bidx & 15;
    const int C0   = cg << 5;            // 32 H-cols
    const int VC0  = cg << 3;            // 8 V-cols
    const int lane = tid & 31;
    const int ks   = lane;               // k-slice: k = m*128 + ks*4 + ki
    const int w    = tid >> 5;           // warp 0..7
    const int rowg = w >> 2;             // 0..1  -> rows rowg*8..+7
    const int colg = w & 3;              // 0..3  -> cols colg*8..+7
    const int hrow0 = rowg << 3;
    // half counters for this row group; this CTA releases its own k-half
    int* barA  = &g_barc[(rgc * 2 + 0) * 32];
    int* barB  = &g_barc[(rgc * 2 + 1) * 32];
    int* mybar = &g_barc[(rgc * 2 + (cg >> 3)) * 32];
    // Wh swizzled unit positions (loop-invariant per lane)
    const int x0u = (colg * 2)     ^ (ks & 7);
    const int x1u = (colg * 2 + 1) ^ (ks & 7);
    // finalize mapping: thread -> h float2 (row i2, col j2)
    const int i2 = tid >> 4;             // 0..15
    const int j2 = (tid & 15) * 2;       // 0..30
    // pre-reduce mapping
    const int ksl  = ks & 15;
    const int rsub = ks >> 4;
    // V out-path owner row
    const int fr = lane >> 2;            // 0..7

    uint32_t smem_u32;
    asm("{ .reg .u64 t0; cvta.to.shared.u64 t0, %1; cvt.u32.u64 %0, t0; }"
        : "=r"(smem_u32) : "l"(sm));

    // ---- prologue: Wh slice (unit-XOR swizzle), Wfc slice --------------
    for (int idx = tid; idx < Hh * 32; idx += NTHR) {
        const int k = idx >> 5, c = idx & 31;
        const int u2 = (c >> 2) ^ ((k >> 2) & 7);
        sm[OFF_WH + (k << 5) + u2 * 4 + (c & 3)] = Wh[k * Hh + C0 + c];
    }
    for (int idx = tid; idx < 8 * Hh; idx += NTHR) {
        const int c = idx >> 9, k = idx & 511;
        sm[OFF_WF + (c << 9) + k] = Wfc[k * Vv + VC0 + c];
    }
    const float2 bfcv = *(const float2*)(bfc + VC0 + colg * 2);
    __syncthreads();

    const float4* wh4 = (const float4*)(sm + OFF_WH);

    for (int t = 0; t <= Ss; ++t) {
        const float* hsrc = g_h[(t + 1) & 1];

        // ---- poll half A (cols 0..255 from CTAs cg 0..7), stage it -----
        if (t > 0) {
            if (lane == 0) {
                const int target = t << 6;     // 8 CTAs x 8 warps
                int v;
                do {
                    asm volatile("ld.acquire.gpu.global.b32 %0, [%1];"
                                 : "=r"(v) : "l"(barA) : "memory");
                } while (v - target < 0);
            }
            __syncwarp();
        }
#pragma unroll
        for (int q = 0; q < 4; ++q) {          // 16 rows x units 0..63
            const int idx = tid + (q << 8);
            const int row = idx >> 6, u = idx & 63;
            const uint32_t sa = smem_u32 +
                (uint32_t)((OFF_SH + (row << 9) + u * 4) * 4);
            asm volatile("cp.async.cg.shared.global [%0], [%1], 16;"
                :: "r"(sa), "l"(((const float4*)(hsrc + ((R0 + row) << 9))) + u));
        }
        asm volatile("cp.async.commit_group;");

        // ---- poll half B (cols 256..511 from CTAs cg 8..15), stage it --
        if (t > 0) {
            if (lane == 0) {
                const int target = t << 6;
                int v;
                do {
                    asm volatile("ld.acquire.gpu.global.b32 %0, [%1];"
                                 : "=r"(v) : "l"(barB) : "memory");
                } while (v - target < 0);
            }
            __syncwarp();
        }
#pragma unroll
        for (int q = 0; q < 4; ++q) {          // 16 rows x units 64..127
            const int idx = tid + (q << 8);
            const int row = idx >> 6, u = 64 + (idx & 63);
            const uint32_t sa = smem_u32 +
                (uint32_t)((OFF_SH + (row << 9) + u * 4) * 4);
            asm volatile("cp.async.cg.shared.global [%0], [%1], 16;"
                :: "r"(sa), "l"(((const float4*)(hsrc + ((R0 + row) << 9))) + u));
        }
        asm volatile("cp.async.commit_group;");

        int tk = 0;
        if (t < Ss) tk = __ldg(x + (R0 + i2) * Ss + t);

        asm volatile("cp.async.wait_group 1;"); // half A landed
        __syncthreads();

        float2 accV[8];
#pragma unroll
        for (int r = 0; r < 8; ++r) accV[r] = make_float2(0.f, 0.f);
        float2 accR[32];
        float2 xa = make_float2(0.f, 0.f);

        if (t < Ss) {
            xa = __ldg((const float2*)(g_xw + tk * Hh + C0 + j2));
#pragma unroll
            for (int p = 0; p < 32; ++p) accR[p] = make_float2(0.f, 0.f);
            // ---- compute m = 0,1 on k-half A (stage B in flight) -------
#pragma unroll
            for (int m = 0; m < 2; ++m) {
                const int ub = (m << 5) + ks;
                float4 h4[8];
#pragma unroll
                for (int r = 0; r < 8; ++r)
                    h4[r] = *(const float4*)(sm + OFF_SH
                              + ((hrow0 + r) << 9) + ub * 4);
                const float4 wfa = *(const float4*)(sm + OFF_WF
                              + ((colg * 2 + 0) << 9) + ub * 4);
                const float4 wfb = *(const float4*)(sm + OFF_WF
                              + ((colg * 2 + 1) << 9) + ub * 4);
#pragma unroll
                for (int ki = 0; ki < 4; ++ki) {
                    const int k = (m << 7) + (ks << 2) + ki;
                    const float4 wa = wh4[(k << 3) + x0u];
                    const float4 wb = wh4[(k << 3) + x1u];
                    const float2 wv = make_float2(((const float*)&wfa)[ki],
                                                  ((const float*)&wfb)[ki]);
#pragma unroll
                    for (int r = 0; r < 8; ++r) {
                        const float hv = ((const float*)&h4[r])[ki];
                        const float2 hh = make_float2(hv, hv);
                        accR[r*4+0] = ffma2(hh, make_float2(wa.x, wa.y), accR[r*4+0]);
                        accR[r*4+1] = ffma2(hh, make_float2(wa.z, wa.w), accR[r*4+1]);
                        accR[r*4+2] = ffma2(hh, make_float2(wb.x, wb.y), accR[r*4+2]);
                        accR[r*4+3] = ffma2(hh, make_float2(wb.z, wb.w), accR[r*4+3]);
                        accV[r]     = ffma2(hh, wv, accV[r]);
                    }
                }
            }
        }

        asm volatile("cp.async.wait_group 0;"); // half B landed
        __syncthreads();

        if (t < Ss) {
            // ---- compute m = 2,3 on k-half B ---------------------------
#pragma unroll
            for (int m = 2; m < 4; ++m) {
                const int ub = (m << 5) + ks;
                float4 h4[8];
#pragma unroll
                for (int r = 0; r < 8; ++r)
                    h4[r] = *(const float4*)(sm + OFF_SH
                              + ((hrow0 + r) << 9) + ub * 4);
                const float4 wfa = *(const float4*)(sm + OFF_WF
                              + ((colg * 2 + 0) << 9) + ub * 4);
                const float4 wfb = *(const float4*)(sm + OFF_WF
                              + ((colg * 2 + 1) << 9) + ub * 4);
#pragma unroll
                for (int ki = 0; ki < 4; ++ki) {
                    const int k = (m << 7) + (ks << 2) + ki;
                    const float4 wa = wh4[(k << 3) + x0u];
                    const float4 wb = wh4[(k << 3) + x1u];
                    const float2 wv = make_float2(((const float*)&wfa)[ki],
                                                  ((const float*)&wfb)[ki]);
#pragma unroll
                    for (int r = 0; r < 8; ++r) {
                        const float hv = ((const float*)&h4[r])[ki];
                        const float2 hh = make_float2(hv, hv);
                        accR[r*4+0] = ffma2(hh, make_float2(wa.x, wa.y), accR[r*4+0]);
                        accR[r*4+1] = ffma2(hh, make_float2(wa.z, wa.w), accR[r*4+1]);
                        accR[r*4+2] = ffma2(hh, make_float2(wb.x, wb.y), accR[r*4+2]);
                        accR[r*4+3] = ffma2(hh, make_float2(wb.z, wb.w), accR[r*4+3]);
                        accV[r]     = ffma2(hh, wv, accV[r]);
                    }
                }
            }
            // ---- one butterfly level (ks ^ 16): 32 -> 16 slices --------
            BFLY2(accR, 32, 16);
            // lane now holds rows hrow0 + rsub*4 + rr (rr=0..3), 8 cols
#pragma unroll
            for (int rr = 0; rr < 4; ++rr) {
                const int row = hrow0 + rsub * 4 + rr;
                float* dst = sm + OFF_RR + ksl * RR_SLICE + row * 36 + colg * 8;
                *(float4*)dst       = make_float4(accR[rr*4+0].x, accR[rr*4+0].y,
                                                  accR[rr*4+1].x, accR[rr*4+1].y);
                *(float4*)(dst + 4) = make_float4(accR[rr*4+2].x, accR[rr*4+2].y,
                                                  accR[rr*4+3].x, accR[rr*4+3].y);
            }
            __syncthreads();
            // ---- reduce 16 slices, tanh, publish, per-warp release -----
            float2 s = xa;
#pragma unroll
            for (int sl = 0; sl < 16; ++sl) {
                const float2 v = *(const float2*)(sm + OFF_RR
                                    + sl * RR_SLICE + i2 * 36 + j2);
                s.x += v.x; s.y += v.y;
            }
            s.x = tanhf(s.x);
            s.y = tanhf(s.y);
            *(float2*)(&g_h[t & 1][((R0 + i2) << 9) + C0 + j2]) = s;
            __syncwarp();
            if (lane == 0)
                asm volatile("red.release.gpu.global.add.s32 [%0], %1;"
                             :: "l"(mybar), "r"(1) : "memory");
        } else {
            // t == Ss: output projection of h(Ss-1) only
#pragma unroll
            for (int m = 0; m < 4; ++m) {
                const int ub = (m << 5) + ks;
                const float4 wfa = *(const float4*)(sm + OFF_WF
                              + ((colg * 2 + 0) << 9) + ub * 4);
                const float4 wfb = *(const float4*)(sm + OFF_WF
                              + ((colg * 2 + 1) << 9) + ub * 4);
#pragma unroll
                for (int r = 0; r < 8; ++r) {
                    const float4 h4 = *(const float4*)(sm + OFF_SH
                              + ((hrow0 + r) << 9) + ub * 4);
#pragma unroll
                    for (int ki = 0; ki < 4; ++ki) {
                        const float hv = ((const float*)&h4)[ki];
                        const float2 wv = make_float2(((const float*)&wfa)[ki],
                                                      ((const float*)&wfb)[ki]);
                        accV[r] = ffma2(make_float2(hv, hv), wv, accV[r]);
                    }
                }
            }
        }

        // ---- out(t-1): in-warp V reduce, off inter-CTA critical path ---
        if (t > 0) {
            BFLY2(accV, 8, 16);
            BFLY2(accV, 4,  8);
            BFLY2(accV, 2,  4);
            accV[0].x += __shfl_xor_sync(0xffffffffu, accV[0].x, 2);
            accV[0].y += __shfl_xor_sync(0xffffffffu, accV[0].y, 2);
            accV[0].x += __shfl_xor_sync(0xffffffffu, accV[0].x, 1);
            accV[0].y += __shfl_xor_sync(0xffffffffu, accV[0].y, 1);
            if ((lane & 3) == 0) {
                float2 o = make_float2(accV[0].x + bfcv.x, accV[0].y + bfcv.y);
                *(float2*)(out + (long)(R0 + hrow0 + fr) * (Ss * Vv)
                           + (long)(t - 1) * Vv + VC0 + colg * 2) = o;
            }
        }
    }
}

extern "C" void kernel_launch(void* const* d_in, const int* in_sizes, int n_in,
                              void* d_out, int out_size) {
    const int*   x   = (const int*)  d_in[0];
    const float* emb = (const float*)d_in[1];
    const float* Wx  = (const float*)d_in[2];
    const float* bx  = (const float*)d_in[3];
    const float* Wh  = (const float*)d_in[4];
    const float* bh  = (const float*)d_in[5];
    const float* Wfc = (const float*)d_in[6];
    const float* bfc = (const float*)d_in[7];
    float* out = (float*)d_out;

    cudaFuncSetAttribute(rnn_persistent,
                         cudaFuncAttributeMaxDynamicSharedMemorySize, SMEM_BYTES);

    xw_kernel<<<Vv, 512>>>(emb, Wx, bx, bh);   // also zeroes h(-1) + counters
    rnn_persistent<<<NBLK, NTHR, SMEM_BYTES>>>(x, Wh, Wfc, bfc, out);
}

// round 14
// speedup vs baseline: 2.5251x; 1.0758x over previous
#include <cuda_runtime.h>
#include <cstdint>

// VanillaRNN B=128,S=2048,E=256,H=512,V=128 fp32 — persistent kernel v10.
// EXACT v6 skeleton (best, 7834us): 8 row-groups x 16 CTAs (CTA = 16 B-rows
// x 32 H-cols), ONE row-group counter polled ONCE per step before staging,
// per-warp 2-row cp.async staging in two overlapped k-halves, SMEM reduce.
// Round-13 deltas (compute-path only):
//  - one in-warp butterfly pre-reduce level -> 16-slice partials
//    (halves reduce-phase crossbar traffic; bank-safe 145-unit stride)
//  - all-lane acquire poll (no lane0/syncwarp handoff)
//  - init merged into xw_kernel

#define Bb   128
#define Ss   2048
#define Vv   128
#define Ee   256
#define Hh   512
#define NBLK 128
#define NTHR 256

#define RR_SLICE 580         // floats per slice (145 16B-units, odd mod 8)

// SMEM offsets (floats)
#define OFF_SH   0                       // h tile: 16 x 512 (plain layout)
#define OFF_WH   8192                    // Wh slice: 512 k x 32 c (unit-XOR)
#define OFF_WF   24576                   // Wfc slice: 8 cols x 512 k
#define OFF_RR   28672                   // partials: 16 x RR_SLICE
#define SMEM_FLOATS (OFF_RR + 16 * RR_SLICE)
#define SMEM_BYTES  (SMEM_FLOATS * 4)

__device__ float g_h[2][Bb * Hh];        // double-buffered hidden state
__device__ float g_xw[Vv * Hh];          // token -> (emb@Wx + bx + bh)
__device__ int   g_bar8[8 * 32];         // per-row-group counters, 128B apart

static __device__ __forceinline__ float2 ffma2(float2 a, float2 b, float2 c) {
    union { float2 f; unsigned long long u; } A, B2, C;
    A.f = a; B2.f = b; C.f = c;
    asm("fma.rn.f32x2 %0, %1, %2, %0;" : "+l"(C.u) : "l"(A.u), "l"(B2.u));
    return C.f;
}

// one recursive-halving butterfly round over float2 array v[m]
#define BFLY2(v, m, s) {                                                  \
    const int  half_ = (m) >> 1;                                          \
    const bool up_ = (lane & (s)) != 0;                                   \
    _Pragma("unroll")                                                     \
    for (int i_ = 0; i_ < half_; ++i_) {                                  \
        float2 d_ = up_ ? v[i_] : v[i_ + half_];                          \
        float2 o_;                                                        \
        o_.x = __shfl_xor_sync(0xffffffffu, d_.x, (s));                   \
        o_.y = __shfl_xor_sync(0xffffffffu, d_.y, (s));                   \
        float2 k_ = up_ ? v[i_ + half_] : v[i_];                          \
        v[i_].x = k_.x + o_.x;                                            \
        v[i_].y = k_.y + o_.y;                                            \
    } }

// g_xw[v][:] = emb[v] @ Wx + bx + bh ; also zeroes h(-1) and counters
__global__ void __launch_bounds__(512) xw_kernel(
    const float* __restrict__ emb, const float* __restrict__ Wx,
    const float* __restrict__ bx,  const float* __restrict__ bh)
{
    __shared__ float se[Ee];
    const int v = blockIdx.x, j = threadIdx.x;
    g_h[1][v * 512 + j] = 0.0f;          // 128 blk x 512 thr = Bb*Hh exactly
    if (v == 0 && j < 8 * 32) g_bar8[j] = 0;
    if (j < Ee) se[j] = emb[v * Ee + j];
    __syncthreads();
    float acc = 0.f;
#pragma unroll 8
    for (int e = 0; e < Ee; ++e) acc = fmaf(se[e], Wx[e * Hh + j], acc);
    g_xw[v * Hh + j] = acc + bx[j] + bh[j];
}

__global__ void __launch_bounds__(NTHR, 1)
rnn_persistent(const int*   __restrict__ x,
               const float* __restrict__ Wh,
               const float* __restrict__ Wfc,
               const float* __restrict__ bfc,
               float* __restrict__ out)
{
    extern __shared__ float sm[];
    const int tid  = threadIdx.x;
    const int bidx = blockIdx.x;
    const int rgc  = bidx >> 4;          // row-group 0..7 (16 B-rows)
    const int R0   = rgc << 4;
    const int cg   = bidx & 15;
    const int C0   = cg << 5;            // 32 H-cols
    const int VC0  = cg << 3;            // 8 V-cols
    const int lane = tid & 31;
    const int ks   = lane;               // k-slice: k = m*128 + ks*4 + ki
    const int w    = tid >> 5;           // warp 0..7
    const int rowg = w >> 2;             // 0..1  -> rows rowg*8..+7
    const int colg = w & 3;              // 0..3  -> cols colg*8..+7
    const int hrow0 = rowg << 3;
    int* bar = &g_bar8[rgc * 32];
    // Wh swizzled unit positions (loop-invariant per lane)
    const int x0u = (colg * 2)     ^ (ks & 7);
    const int x1u = (colg * 2 + 1) ^ (ks & 7);
    // finalize mapping: thread -> h float2 (row i2, col j2)
    const int i2 = tid >> 4;             // 0..15
    const int j2 = (tid & 15) * 2;       // 0..30
    // pre-reduce mapping (after BFLY over s=16)
    const int ksl  = ks & 15;
    const int rsub = ks >> 4;            // 0: rows 0..3, 1: rows 4..7 of rowg
    // V out-path owner row
    const int fr = lane >> 2;            // 0..7

    uint32_t smem_u32;
    asm("{ .reg .u64 t0; cvta.to.shared.u64 t0, %1; cvt.u32.u64 %0, t0; }"
        : "=r"(smem_u32) : "l"(sm));

    // ---- prologue: Wh slice (unit-XOR swizzle), Wfc slice --------------
    for (int idx = tid; idx < Hh * 32; idx += NTHR) {
        const int k = idx >> 5, c = idx & 31;
        const int u2 = (c >> 2) ^ ((k >> 2) & 7);
        sm[OFF_WH + (k << 5) + u2 * 4 + (c & 3)] = Wh[k * Hh + C0 + c];
    }
    for (int idx = tid; idx < 8 * Hh; idx += NTHR) {
        const int c = idx >> 9, k = idx & 511;
        sm[OFF_WF + (c << 9) + k] = Wfc[k * Vv + VC0 + c];
    }
    const float2 bfcv = *(const float2*)(bfc + VC0 + colg * 2);
    __syncthreads();

    const float4* wh4 = (const float4*)(sm + OFF_WH);

    for (int t = 0; t <= Ss; ++t) {
        // ---- all-lane acquire poll (domain: 16 CTAs x 8 warps = 128) ---
        if (t > 0) {
            const int target = t << 7;
            int v;
            do {
                asm volatile("ld.acquire.gpu.global.b32 %0, [%1];"
                             : "=r"(v) : "l"(bar) : "memory");
            } while (v - target < 0);
        }
        // ---- stage h(t-1): warp w stages rows 2w,2w+1; two k-halves ----
        const float* hsrc = g_h[(t + 1) & 1];
#pragma unroll
        for (int j = 0; j < 4; ++j) {            // half A: units 0..63
            const int idx = lane + (j << 5);
            const int row = 2 * w + (idx >> 6);
            const int u   = idx & 63;
            const uint32_t sa = smem_u32 +
                (uint32_t)((OFF_SH + (row << 9) + u * 4) * 4);
            asm volatile("cp.async.cg.shared.global [%0], [%1], 16;"
                :: "r"(sa), "l"(((const float4*)(hsrc + ((R0 + row) << 9))) + u));
        }
        asm volatile("cp.async.commit_group;");
#pragma unroll
        for (int j = 0; j < 4; ++j) {            // half B: units 64..127
            const int idx = lane + (j << 5);
            const int row = 2 * w + (idx >> 6);
            const int u   = 64 + (idx & 63);
            const uint32_t sa = smem_u32 +
                (uint32_t)((OFF_SH + (row << 9) + u * 4) * 4);
            asm volatile("cp.async.cg.shared.global [%0], [%1], 16;"
                :: "r"(sa), "l"(((const float4*)(hsrc + ((R0 + row) << 9))) + u));
        }
        asm volatile("cp.async.commit_group;");

        int tk = 0;
        if (t < Ss) tk = __ldg(x + (R0 + i2) * Ss + t);

        asm volatile("cp.async.wait_group 1;");  // half A ready
        __syncthreads();

        float2 accV[8];
#pragma unroll
        for (int r = 0; r < 8; ++r) accV[r] = make_float2(0.f, 0.f);
        float2 accR[32];
        float2 xa = make_float2(0.f, 0.f);

        if (t < Ss) {
            // prefetch xw[token] (consumed in reduce, latency hidden)
            xa = __ldg((const float2*)(g_xw + tk * Hh + C0 + j2));
#pragma unroll
            for (int p = 0; p < 32; ++p) accR[p] = make_float2(0.f, 0.f);
            // ---- compute m = 0,1 on k-half A ---------------------------
#pragma unroll
            for (int m = 0; m < 2; ++m) {
                const int ub = (m << 5) + ks;
                float4 h4[8];
#pragma unroll
                for (int r = 0; r < 8; ++r)
                    h4[r] = *(const float4*)(sm + OFF_SH
                              + ((hrow0 + r) << 9) + ub * 4);
                const float4 wfa = *(const float4*)(sm + OFF_WF
                              + ((colg * 2 + 0) << 9) + ub * 4);
                const float4 wfb = *(const float4*)(sm + OFF_WF
                              + ((colg * 2 + 1) << 9) + ub * 4);
#pragma unroll
                for (int ki = 0; ki < 4; ++ki) {
                    const int k = (m << 7) + (ks << 2) + ki;
                    const float4 wa = wh4[(k << 3) + x0u];
                    const float4 wb = wh4[(k << 3) + x1u];
                    const float2 wv = make_float2(((const float*)&wfa)[ki],
                                                  ((const float*)&wfb)[ki]);
#pragma unroll
                    for (int r = 0; r < 8; ++r) {
                        const float hv = ((const float*)&h4[r])[ki];
                        const float2 hh = make_float2(hv, hv);
                        accR[r*4+0] = ffma2(hh, make_float2(wa.x, wa.y), accR[r*4+0]);
                        accR[r*4+1] = ffma2(hh, make_float2(wa.z, wa.w), accR[r*4+1]);
                        accR[r*4+2] = ffma2(hh, make_float2(wb.x, wb.y), accR[r*4+2]);
                        accR[r*4+3] = ffma2(hh, make_float2(wb.z, wb.w), accR[r*4+3]);
                        accV[r]     = ffma2(hh, wv, accV[r]);
                    }
                }
            }
        }

        asm volatile("cp.async.wait_group 0;");  // half B ready
        __syncthreads();

        if (t < Ss) {
            // ---- compute m = 2,3 on k-half B ---------------------------
#pragma unroll
            for (int m = 2; m < 4; ++m) {
                const int ub = (m << 5) + ks;
                float4 h4[8];
#pragma unroll
                for (int r = 0; r < 8; ++r)
                    h4[r] = *(const float4*)(sm + OFF_SH
                              + ((hrow0 + r) << 9) + ub * 4);
                const float4 wfa = *(const float4*)(sm + OFF_WF
                              + ((colg * 2 + 0) << 9) + ub * 4);
                const float4 wfb = *(const float4*)(sm + OFF_WF
                              + ((colg * 2 + 1) << 9) + ub * 4);
#pragma unroll
                for (int ki = 0; ki < 4; ++ki) {
                    const int k = (m << 7) + (ks << 2) + ki;
                    const float4 wa = wh4[(k << 3) + x0u];
                    const float4 wb = wh4[(k << 3) + x1u];
                    const float2 wv = make_float2(((const float*)&wfa)[ki],
                                                  ((const float*)&wfb)[ki]);
#pragma unroll
                    for (int r = 0; r < 8; ++r) {
                        const float hv = ((const float*)&h4[r])[ki];
                        const float2 hh = make_float2(hv, hv);
                        accR[r*4+0] = ffma2(hh, make_float2(wa.x, wa.y), accR[r*4+0]);
                        accR[r*4+1] = ffma2(hh, make_float2(wa.z, wa.w), accR[r*4+1]);
                        accR[r*4+2] = ffma2(hh, make_float2(wb.x, wb.y), accR[r*4+2]);
                        accR[r*4+3] = ffma2(hh, make_float2(wb.z, wb.w), accR[r*4+3]);
                        accV[r]     = ffma2(hh, wv, accV[r]);
                    }
                }
            }
            // ---- one butterfly level (ks ^ 16): 32 -> 16 slices --------
            BFLY2(accR, 32, 16);
            // lane holds rows hrow0 + rsub*4 + rr (rr=0..3), its 8 cols
#pragma unroll
            for (int rr = 0; rr < 4; ++rr) {
                const int row = hrow0 + rsub * 4 + rr;
                float* dst = sm + OFF_RR + ksl * RR_SLICE + row * 36 + colg * 8;
                *(float4*)dst       = make_float4(accR[rr*4+0].x, accR[rr*4+0].y,
                                                  accR[rr*4+1].x, accR[rr*4+1].y);
                *(float4*)(dst + 4) = make_float4(accR[rr*4+2].x, accR[rr*4+2].y,
                                                  accR[rr*4+3].x, accR[rr*4+3].y);
            }
            __syncthreads();
            // ---- reduce 16 slices, tanh, publish, per-warp release -----
            float2 s = xa;
#pragma unroll
            for (int sl = 0; sl < 16; ++sl) {
                const float2 v = *(const float2*)(sm + OFF_RR
                                    + sl * RR_SLICE + i2 * 36 + j2);
                s.x += v.x; s.y += v.y;
            }
            s.x = tanhf(s.x);
            s.y = tanhf(s.y);
            *(float2*)(&g_h[t & 1][((R0 + i2) << 9) + C0 + j2]) = s;
            __syncwarp();
            if (lane == 0)
                asm volatile("red.release.gpu.global.add.s32 [%0], %1;"
                             :: "l"(bar), "r"(1) : "memory");
        } else {
            // t == Ss: output projection of h(Ss-1) only
#pragma unroll
            for (int m = 0; m < 4; ++m) {
                const int ub = (m << 5) + ks;
                const float4 wfa = *(const float4*)(sm + OFF_WF
                              + ((colg * 2 + 0) << 9) + ub * 4);
                const float4 wfb = *(const float4*)(sm + OFF_WF
                              + ((colg * 2 + 1) << 9) + ub * 4);
#pragma unroll
                for (int r = 0; r < 8; ++r) {
                    const float4 h4 = *(const float4*)(sm + OFF_SH
                              + ((hrow0 + r) << 9) + ub * 4);
#pragma unroll
                    for (int ki = 0; ki < 4; ++ki) {
                        const float hv = ((const float*)&h4)[ki];
                        const float2 wv = make_float2(((const float*)&wfa)[ki],
                                                      ((const float*)&wfb)[ki]);
                        accV[r] = ffma2(make_float2(hv, hv), wv, accV[r]);
                    }
                }
            }
        }

        // ---- out(t-1): in-warp V reduce, off inter-CTA critical path ---
        if (t > 0) {
            BFLY2(accV, 8, 16);
            BFLY2(accV, 4,  8);
            BFLY2(accV, 2,  4);
            accV[0].x += __shfl_xor_sync(0xffffffffu, accV[0].x, 2);
            accV[0].y += __shfl_xor_sync(0xffffffffu, accV[0].y, 2);
            accV[0].x += __shfl_xor_sync(0xffffffffu, accV[0].x, 1);
            accV[0].y += __shfl_xor_sync(0xffffffffu, accV[0].y, 1);
            if ((lane & 3) == 0) {
                float2 o = make_float2(accV[0].x + bfcv.x, accV[0].y + bfcv.y);
                *(float2*)(out + (long)(R0 + hrow0 + fr) * (Ss * Vv)
                           + (long)(t - 1) * Vv + VC0 + colg * 2) = o;
            }
        }
    }
}

extern "C" void kernel_launch(void* const* d_in, const int* in_sizes, int n_in,
                              void* d_out, int out_size) {
    const int*   x   = (const int*)  d_in[0];
    const float* emb = (const float*)d_in[1];
    const float* Wx  = (const float*)d_in[2];
    const float* bx  = (const float*)d_in[3];
    const float* Wh  = (const float*)d_in[4];
    const float* bh  = (const float*)d_in[5];
    const float* Wfc = (const float*)d_in[6];
    const float* bfc = (const float*)d_in[7];
    float* out = (float*)d_out;

    cudaFuncSetAttribute(rnn_persistent,
                         cudaFuncAttributeMaxDynamicSharedMemorySize, SMEM_BYTES);

    xw_kernel<<<Vv, 512>>>(emb, Wx, bx, bh);   // also zeroes h(-1) + counters
    rnn_persistent<<<NBLK, NTHR, SMEM_BYTES>>>(x, Wh, Wfc, bfc, out);
}